// round 5
// baseline (speedup 1.0000x reference)
#include <cuda_runtime.h>
#include <math.h>

// Problem constants (fixed shapes from setup_inputs)
#define BS      4
#define NHEAD   8
#define HH_TOT  32          // BS*NHEAD
#define T_LEN   1024
#define CH      64
#define NOBJ    8
#define QT      32          // flash q-tile
#define KT      64          // flash k-tile

// ---------------- scratch (device globals; no allocs allowed) ----------------
__device__ float g_Qn[HH_TOT * T_LEN * CH];
__device__ float g_Kn[HH_TOT * T_LEN * CH];
__device__ float g_Vn[HH_TOT * T_LEN * CH];
__device__ float g_Qf[HH_TOT * T_LEN * CH];
__device__ float g_Kf[HH_TOT * T_LEN * CH];
__device__ float g_Vf[HH_TOT * T_LEN * CH];
__device__ float g_anull[HH_TOT * T_LEN * CH];
__device__ float g_afg[HH_TOT * T_LEN * CH];
__device__ int   g_regbox[BS * NOBJ * 4];   // i0,i1,j0,j1 (clamped to 32)
__device__ float g_cnt[BS * T_LEN];

// ---------------- prep: region boxes + per-token overlap counter ----------------
__global__ __launch_bounds__(256)
void prep_kernel(const float* __restrict__ bb) {
    __shared__ int sreg[BS * NOBJ][4];
    const int tid = threadIdx.x;
    if (tid < BS * NOBJ) {
        const float* p = bb + tid * 5;
        float x = p[0], y = p[1], w = p[2], h = p[3];
        int i0 = (int)fminf(31.0f, floorf(y * 32.0f));
        int j0 = (int)fminf(31.0f, floorf(x * 32.0f));
        int hh = (int)fmaxf(1.0f, ceilf(h * 32.0f));
        int ww = (int)fmaxf(1.0f, ceilf(w * 32.0f));
        int i1 = min(32, i0 + hh);
        int j1 = min(32, j0 + ww);
        g_regbox[tid * 4 + 0] = i0;  g_regbox[tid * 4 + 1] = i1;
        g_regbox[tid * 4 + 2] = j0;  g_regbox[tid * 4 + 3] = j1;
        sreg[tid][0] = i0; sreg[tid][1] = i1; sreg[tid][2] = j0; sreg[tid][3] = j1;
    }
    __syncthreads();
    for (int idx = tid; idx < BS * T_LEN; idx += blockDim.x) {
        int b = idx / T_LEN, t = idx % T_LEN;
        int i = t >> 5, j = t & 31;
        float c = 0.0f;
        #pragma unroll
        for (int o = 0; o < NOBJ; o++) {
            const int* r = sreg[b * NOBJ + o];
            if (i >= r[0] && i < r[1] && j >= r[2] && j < r[3]) c += 1.0f;
        }
        g_cnt[idx] = c;
    }
}

__global__ __launch_bounds__(256)
void zero_afg_kernel() {
    int i = blockIdx.x * 256 + threadIdx.x;          // float4 index
    float4* p = (float4*)g_afg;
    if (i < (HH_TOT * T_LEN * CH) / 4) p[i] = make_float4(0.f, 0.f, 0.f, 0.f);
}

// ---------------- combine: qkv split + prompt projection GEMM ----------------
// Y[c][t] = sum_e W[cg0+c][e] * emb[b][e][t0+t]; out = (Y + qkv) * (part==0 ? 0.125 : 1)
// grid (24 cg-tiles, 16 t-tiles, 8 = b*2+var), 256 threads
__global__ __launch_bounds__(256)
void combine_kernel(const float* __restrict__ qkv, const float* __restrict__ nemb,
                    const float* __restrict__ pemb, const float* __restrict__ W) {
    __shared__ float Ws[64 * 65];
    __shared__ __align__(16) float Es[64 * 68];
    const int g   = blockIdx.x;            // 0..23
    const int t0  = blockIdx.y * 64;
    const int zv  = blockIdx.z;
    const int b   = zv >> 1, var = zv & 1;
    const int head = g / 3, part = g % 3;
    const int cg0  = g * 64;
    const float* emb = (var ? pemb : nemb) + b * 64 * 1024;
    const int tid = threadIdx.x;

    for (int i = tid; i < 4096; i += 256) {
        int c = i >> 6, e = i & 63;
        Ws[c * 65 + e] = W[(cg0 + c) * 64 + e];
    }
    for (int i = tid; i < 4096; i += 256) {
        int e = i >> 6, t = i & 63;
        Es[e * 68 + t] = emb[e * 1024 + t0 + t];
    }
    __syncthreads();

    const int c = tid & 63, tg = tid >> 6;   // tg 0..3, 16 t each
    float acc[16];
    #pragma unroll
    for (int i = 0; i < 16; i++) acc[i] = 0.0f;

    #pragma unroll 4
    for (int e = 0; e < 64; e++) {
        float w = Ws[c * 65 + e];
        const float4* row = (const float4*)(Es + e * 68 + tg * 16);
        float4 a0 = row[0], a1 = row[1], a2 = row[2], a3 = row[3];
        acc[0]  += w * a0.x; acc[1]  += w * a0.y; acc[2]  += w * a0.z; acc[3]  += w * a0.w;
        acc[4]  += w * a1.x; acc[5]  += w * a1.y; acc[6]  += w * a1.z; acc[7]  += w * a1.w;
        acc[8]  += w * a2.x; acc[9]  += w * a2.y; acc[10] += w * a2.z; acc[11] += w * a2.w;
        acc[12] += w * a3.x; acc[13] += w * a3.y; acc[14] += w * a3.z; acc[15] += w * a3.w;
    }
    __syncthreads();
    // reuse Es to stage the qkv tile (row = c, fast = t, coalesced reads)
    const float* qk = qkv + (size_t)b * 1536 * 1024 + (size_t)cg0 * 1024 + t0;
    for (int i = tid; i < 4096; i += 256) {
        int cc = i >> 6, t = i & 63;
        Es[cc * 68 + t] = qk[cc * 1024 + t];
    }
    __syncthreads();

    float* dst;
    if (var == 0) dst = (part == 0 ? g_Qn : (part == 1 ? g_Kn : g_Vn));
    else          dst = (part == 0 ? g_Qf : (part == 1 ? g_Kf : g_Vf));
    dst += (b * NHEAD + head) * T_LEN * CH;
    const float sc = (part == 0) ? 0.125f : 1.0f;   // scale^2 = ch^-0.5 folded into Q
    #pragma unroll
    for (int i = 0; i < 16; i++) {
        int t = tg * 16 + i;
        dst[(t0 + t) * CH + c] = (acc[i] + Es[c * 68 + t]) * sc;
    }
}

// ---------------- flash attention cores ----------------
// 128 threads: ty=tid>>4 (rows r0=ty*4 of 32), tx=tid&15 (cols s0/c0=tx*4 of 64)
__device__ __forceinline__ float redmax16(float v) {
    #pragma unroll
    for (int off = 8; off; off >>= 1) v = fmaxf(v, __shfl_xor_sync(0xffffffffu, v, off));
    return v;
}
__device__ __forceinline__ float redsum16(float v) {
    #pragma unroll
    for (int off = 8; off; off >>= 1) v += __shfl_xor_sync(0xffffffffu, v, off);
    return v;
}

__global__ __launch_bounds__(128)
void flash_null_kernel() {
    __shared__ __align__(16) float Qs[QT * 68];
    __shared__ __align__(16) float KPs[KT * 68];
    __shared__ __align__(16) float Vs[KT * 68];
    const int bh = blockIdx.y;
    const int q0 = blockIdx.x * QT;
    const float* Qp = g_Qn + (size_t)bh * T_LEN * CH;
    const float* Kp = g_Kn + (size_t)bh * T_LEN * CH;
    const float* Vp = g_Vn + (size_t)bh * T_LEN * CH;
    const int tid = threadIdx.x;
    const int ty = tid >> 4, tx = tid & 15;
    const int r0 = ty * 4, s0 = tx * 4;
    float4* Qs4 = (float4*)Qs;
    float4* KPs4 = (float4*)KPs;
    float4* Vs4 = (float4*)Vs;

    {   // load Q tile (coalesced float4)
        const float4* Qg = (const float4*)(Qp + (size_t)q0 * CH);
        for (int i = tid; i < QT * 16; i += 128) {
            int r = i >> 4, c4 = i & 15;
            Qs4[r * 17 + c4] = Qg[r * 16 + c4];
        }
    }
    float O[4][4];
    float m[4], l[4];
    #pragma unroll
    for (int i = 0; i < 4; i++) {
        m[i] = -1e30f; l[i] = 0.0f;
        #pragma unroll
        for (int j = 0; j < 4; j++) O[i][j] = 0.0f;
    }

    for (int kt = 0; kt < T_LEN / KT; kt++) {
        __syncthreads();
        const float4* Kg = (const float4*)(Kp + (size_t)kt * KT * CH);
        const float4* Vg = (const float4*)(Vp + (size_t)kt * KT * CH);
        for (int i = tid; i < KT * 16; i += 128) {
            int r = i >> 4, c4 = i & 15;
            KPs4[r * 17 + c4] = Kg[r * 16 + c4];
            Vs4[r * 17 + c4]  = Vg[r * 16 + c4];
        }
        __syncthreads();

        float S[4][4];
        #pragma unroll
        for (int i = 0; i < 4; i++)
            #pragma unroll
            for (int j = 0; j < 4; j++) S[i][j] = 0.0f;

        #pragma unroll
        for (int c4 = 0; c4 < 16; c4++) {
            float4 qf[4], kf[4];
            #pragma unroll
            for (int i = 0; i < 4; i++) qf[i] = Qs4[(r0 + i) * 17 + c4];
            #pragma unroll
            for (int j = 0; j < 4; j++) kf[j] = KPs4[(s0 + j) * 17 + c4];
            #pragma unroll
            for (int i = 0; i < 4; i++)
                #pragma unroll
                for (int j = 0; j < 4; j++)
                    S[i][j] += qf[i].x * kf[j].x + qf[i].y * kf[j].y
                             + qf[i].z * kf[j].z + qf[i].w * kf[j].w;
        }

        // online softmax
        #pragma unroll
        for (int i = 0; i < 4; i++) {
            float mx = fmaxf(fmaxf(S[i][0], S[i][1]), fmaxf(S[i][2], S[i][3]));
            mx = redmax16(mx);
            float mn = fmaxf(m[i], mx);
            float co = __expf(m[i] - mn);
            m[i] = mn;
            float rs = 0.0f;
            #pragma unroll
            for (int j = 0; j < 4; j++) { S[i][j] = __expf(S[i][j] - mn); rs += S[i][j]; }
            rs = redsum16(rs);
            l[i] = l[i] * co + rs;
            #pragma unroll
            for (int j = 0; j < 4; j++) O[i][j] *= co;
        }
        __syncthreads();             // everyone done reading K
        #pragma unroll
        for (int i = 0; i < 4; i++)  // stash P over K's smem
            KPs4[(r0 + i) * 17 + tx] = make_float4(S[i][0], S[i][1], S[i][2], S[i][3]);
        __syncthreads();

        #pragma unroll
        for (int s4 = 0; s4 < 16; s4++) {
            float4 vf[4];
            #pragma unroll
            for (int k2 = 0; k2 < 4; k2++) vf[k2] = Vs4[(s4 * 4 + k2) * 17 + tx];
            #pragma unroll
            for (int i = 0; i < 4; i++) {
                float4 pf = KPs4[(r0 + i) * 17 + s4];
                O[i][0] += pf.x * vf[0].x + pf.y * vf[1].x + pf.z * vf[2].x + pf.w * vf[3].x;
                O[i][1] += pf.x * vf[0].y + pf.y * vf[1].y + pf.z * vf[2].y + pf.w * vf[3].y;
                O[i][2] += pf.x * vf[0].z + pf.y * vf[1].z + pf.z * vf[2].z + pf.w * vf[3].z;
                O[i][3] += pf.x * vf[0].w + pf.y * vf[1].w + pf.z * vf[2].w + pf.w * vf[3].w;
            }
        }
    }

    float* Op = g_anull + (size_t)bh * T_LEN * CH;
    #pragma unroll
    for (int i = 0; i < 4; i++) {
        float inv = 1.0f / l[i];
        ((float4*)(Op + (size_t)(q0 + r0 + i) * CH))[tx] =
            make_float4(O[i][0] * inv, O[i][1] * inv, O[i][2] * inv, O[i][3] * inv);
    }
}

// foreground: per (b,obj) region-restricted attention, accumulated with atomics
__global__ __launch_bounds__(128)
void flash_fg_kernel() {
    __shared__ __align__(16) float Qs[QT * 68];
    __shared__ __align__(16) float KPs[KT * 68];
    __shared__ __align__(16) float Vs[KT * 68];
    const int bh = blockIdx.z;
    const int o  = blockIdx.y;
    const int b  = bh >> 3;
    const int* box = g_regbox + (b * NOBJ + o) * 4;
    const int i0 = box[0], i1 = box[1], j0 = box[2], j1 = box[3];
    const int rw = j1 - j0;
    const int nR = (i1 - i0) * rw;
    const int qbase = blockIdx.x * QT;
    if (qbase >= nR) return;

    const float* Qp = g_Qf + (size_t)bh * T_LEN * CH;
    const float* Kp = g_Kf + (size_t)bh * T_LEN * CH;
    const float* Vp = g_Vf + (size_t)bh * T_LEN * CH;
    const int tid = threadIdx.x;
    const int ty = tid >> 4, tx = tid & 15;
    const int r0 = ty * 4, s0 = tx * 4;
    float4* Qs4 = (float4*)Qs;
    float4* KPs4 = (float4*)KPs;
    float4* Vs4 = (float4*)Vs;

    for (int i = tid; i < QT * 16; i += 128) {
        int r = i >> 4, c4 = i & 15;
        int u = qbase + r;
        float4 val = make_float4(0.f, 0.f, 0.f, 0.f);
        if (u < nR) {
            int t = (i0 + u / rw) * 32 + j0 + u % rw;
            val = ((const float4*)(Qp + (size_t)t * CH))[c4];
        }
        Qs4[r * 17 + c4] = val;
    }

    float O[4][4];
    float m[4], l[4];
    #pragma unroll
    for (int i = 0; i < 4; i++) {
        m[i] = -1e30f; l[i] = 0.0f;
        #pragma unroll
        for (int j = 0; j < 4; j++) O[i][j] = 0.0f;
    }

    const int nkt = (nR + KT - 1) / KT;
    for (int kt = 0; kt < nkt; kt++) {
        __syncthreads();
        for (int i = tid; i < KT * 16; i += 128) {
            int r = i >> 4, c4 = i & 15;
            int s = kt * KT + r;
            float4 kv = make_float4(0.f, 0.f, 0.f, 0.f);
            float4 vv = kv;
            if (s < nR) {
                int t = (i0 + s / rw) * 32 + j0 + s % rw;
                kv = ((const float4*)(Kp + (size_t)t * CH))[c4];
                vv = ((const float4*)(Vp + (size_t)t * CH))[c4];
            }
            KPs4[r * 17 + c4] = kv;
            Vs4[r * 17 + c4]  = vv;
        }
        __syncthreads();

        float S[4][4];
        #pragma unroll
        for (int i = 0; i < 4; i++)
            #pragma unroll
            for (int j = 0; j < 4; j++) S[i][j] = 0.0f;

        #pragma unroll
        for (int c4 = 0; c4 < 16; c4++) {
            float4 qf[4], kf[4];
            #pragma unroll
            for (int i = 0; i < 4; i++) qf[i] = Qs4[(r0 + i) * 17 + c4];
            #pragma unroll
            for (int j = 0; j < 4; j++) kf[j] = KPs4[(s0 + j) * 17 + c4];
            #pragma unroll
            for (int i = 0; i < 4; i++)
                #pragma unroll
                for (int j = 0; j < 4; j++)
                    S[i][j] += qf[i].x * kf[j].x + qf[i].y * kf[j].y
                             + qf[i].z * kf[j].z + qf[i].w * kf[j].w;
        }
        // mask columns beyond region
        #pragma unroll
        for (int j = 0; j < 4; j++)
            if (kt * KT + s0 + j >= nR) {
                #pragma unroll
                for (int i = 0; i < 4; i++) S[i][j] = -1e30f;
            }

        #pragma unroll
        for (int i = 0; i < 4; i++) {
            float mx = fmaxf(fmaxf(S[i][0], S[i][1]), fmaxf(S[i][2], S[i][3]));
            mx = redmax16(mx);
            float mn = fmaxf(m[i], mx);
            float co = __expf(m[i] - mn);
            m[i] = mn;
            float rs = 0.0f;
            #pragma unroll
            for (int j = 0; j < 4; j++) { S[i][j] = __expf(S[i][j] - mn); rs += S[i][j]; }
            rs = redsum16(rs);
            l[i] = l[i] * co + rs;
            #pragma unroll
            for (int j = 0; j < 4; j++) O[i][j] *= co;
        }
        __syncthreads();
        #pragma unroll
        for (int i = 0; i < 4; i++)
            KPs4[(r0 + i) * 17 + tx] = make_float4(S[i][0], S[i][1], S[i][2], S[i][3]);
        __syncthreads();

        #pragma unroll
        for (int s4 = 0; s4 < 16; s4++) {
            float4 vf[4];
            #pragma unroll
            for (int k2 = 0; k2 < 4; k2++) vf[k2] = Vs4[(s4 * 4 + k2) * 17 + tx];
            #pragma unroll
            for (int i = 0; i < 4; i++) {
                float4 pf = KPs4[(r0 + i) * 17 + s4];
                O[i][0] += pf.x * vf[0].x + pf.y * vf[1].x + pf.z * vf[2].x + pf.w * vf[3].x;
                O[i][1] += pf.x * vf[0].y + pf.y * vf[1].y + pf.z * vf[2].y + pf.w * vf[3].y;
                O[i][2] += pf.x * vf[0].z + pf.y * vf[1].z + pf.z * vf[2].z + pf.w * vf[3].z;
                O[i][3] += pf.x * vf[0].w + pf.y * vf[1].w + pf.z * vf[2].w + pf.w * vf[3].w;
            }
        }
    }

    float* Ap = g_afg + (size_t)bh * T_LEN * CH;
    #pragma unroll
    for (int i = 0; i < 4; i++) {
        int u = qbase + r0 + i;
        if (u < nR) {
            int t = (i0 + u / rw) * 32 + j0 + u % rw;
            float inv = 1.0f / l[i];
            float* dp = Ap + (size_t)t * CH + s0;   // s0 == tx*4 == c0
            atomicAdd(dp + 0, O[i][0] * inv);
            atomicAdd(dp + 1, O[i][1] * inv);
            atomicAdd(dp + 2, O[i][2] * inv);
            atomicAdd(dp + 3, O[i][3] * inv);
        }
    }
}

// ---------------- finalize: select + divide + transpose to (bs, 512, T) ----------------
__global__ __launch_bounds__(256)
void finalize_kernel(float* __restrict__ out) {
    __shared__ float sm[64 * 65];
    const int bh = blockIdx.y;
    const int t0 = blockIdx.x * 64;
    const int b = bh >> 3, h = bh & 7;
    const float* An = g_anull + (size_t)bh * T_LEN * CH;
    const float* Af = g_afg   + (size_t)bh * T_LEN * CH;
    const float* Cn = g_cnt + b * T_LEN;
    const int tid = threadIdx.x;
    for (int i = tid; i < 4096; i += 256) {
        int tt = i >> 6, c = i & 63;
        int t = t0 + tt;
        float cnt = Cn[t];
        float v = (cnt > 0.5f) ? Af[(size_t)t * CH + c] / cnt : An[(size_t)t * CH + c];
        sm[tt * 65 + c] = v;
    }
    __syncthreads();
    float* op = out + (size_t)b * 512 * 1024 + (size_t)h * 64 * 1024 + t0;
    for (int i = tid; i < 4096; i += 256) {
        int c = i >> 6, tt = i & 63;
        op[(size_t)c * 1024 + tt] = sm[tt * 65 + c];
    }
}

// ---------------- launch ----------------
extern "C" void kernel_launch(void* const* d_in, const int* in_sizes, int n_in,
                              void* d_out, int out_size) {
    const float* qkv  = (const float*)d_in[0];
    const float* bb   = (const float*)d_in[1];
    const float* nemb = (const float*)d_in[2];
    const float* pemb = (const float*)d_in[3];
    const float* W    = (const float*)d_in[4];
    float* out = (float*)d_out;

    prep_kernel<<<1, 256>>>(bb);
    zero_afg_kernel<<<(HH_TOT * T_LEN * CH / 4 + 255) / 256, 256>>>();
    combine_kernel<<<dim3(24, 16, 8), 256>>>(qkv, nemb, pemb, W);
    flash_null_kernel<<<dim3(T_LEN / QT, HH_TOT), 128>>>();
    flash_fg_kernel<<<dim3(T_LEN / QT, NOBJ, HH_TOT), 128>>>();
    finalize_kernel<<<dim3(T_LEN / 64, HH_TOT), 256>>>(out);
}

// round 6
// speedup vs baseline: 1.3872x; 1.3872x over previous
#include <cuda_runtime.h>
#include <math.h>

// Problem constants (fixed shapes from setup_inputs)
#define BS      4
#define NHEAD   8
#define HH_TOT  32          // BS*NHEAD
#define T_LEN   1024
#define CH      64
#define NOBJ    8

// flash tile config (v2 core)
#define QT      64          // q rows per block
#define KT      128         // k cols per tile
// smem layout (floats): Qs[64][65] | KT_s/Ps[64][130] | Vs[128][64]
#define QS_OFF  0
#define KT_OFF  (64 * 65)                   // 4160
#define V_OFF   (KT_OFF + 64 * 130)         // 12480
#define SMEM_FLOATS (V_OFF + 128 * 64)      // 20672
#define SMEM_BYTES  (SMEM_FLOATS * 4)       // 82688

typedef unsigned long long ull;

// ---------------- f32x2 helpers ----------------
__device__ __forceinline__ ull pk2(float lo, float hi) {
    ull r; asm("mov.b64 %0, {%1, %2};" : "=l"(r) : "f"(lo), "f"(hi)); return r;
}
__device__ __forceinline__ void upk2(ull v, float& lo, float& hi) {
    asm("mov.b64 {%0, %1}, %2;" : "=f"(lo), "=f"(hi) : "l"(v));
}
__device__ __forceinline__ ull fma2(ull a, ull b, ull c) {
    ull d; asm("fma.rn.f32x2 %0, %1, %2, %3;" : "=l"(d) : "l"(a), "l"(b), "l"(c)); return d;
}
__device__ __forceinline__ ull mul2(ull a, ull b) {
    ull d; asm("mul.rn.f32x2 %0, %1, %2;" : "=l"(d) : "l"(a), "l"(b)); return d;
}

// ---------------- scratch (device globals; no allocs allowed) ----------------
__device__ float g_Qn[HH_TOT * T_LEN * CH];
__device__ float g_Kn[HH_TOT * T_LEN * CH];
__device__ float g_Vn[HH_TOT * T_LEN * CH];
__device__ float g_Qf[HH_TOT * T_LEN * CH];
__device__ float g_Kf[HH_TOT * T_LEN * CH];
__device__ float g_Vf[HH_TOT * T_LEN * CH];
__device__ float g_anull[HH_TOT * T_LEN * CH];
__device__ float g_afg[HH_TOT * T_LEN * CH];
__device__ int   g_regbox[BS * NOBJ * 4];   // i0,i1,j0,j1 (clamped to 32)
__device__ float g_cnt[BS * T_LEN];

// ---------------- prep: region boxes + per-token overlap counter ----------------
__global__ __launch_bounds__(256)
void prep_kernel(const float* __restrict__ bb) {
    __shared__ int sreg[BS * NOBJ][4];
    const int tid = threadIdx.x;
    if (tid < BS * NOBJ) {
        const float* p = bb + tid * 5;
        float x = p[0], y = p[1], w = p[2], h = p[3];
        int i0 = (int)fminf(31.0f, floorf(y * 32.0f));
        int j0 = (int)fminf(31.0f, floorf(x * 32.0f));
        int hh = (int)fmaxf(1.0f, ceilf(h * 32.0f));
        int ww = (int)fmaxf(1.0f, ceilf(w * 32.0f));
        int i1 = min(32, i0 + hh);
        int j1 = min(32, j0 + ww);
        g_regbox[tid * 4 + 0] = i0;  g_regbox[tid * 4 + 1] = i1;
        g_regbox[tid * 4 + 2] = j0;  g_regbox[tid * 4 + 3] = j1;
        sreg[tid][0] = i0; sreg[tid][1] = i1; sreg[tid][2] = j0; sreg[tid][3] = j1;
    }
    __syncthreads();
    for (int idx = tid; idx < BS * T_LEN; idx += blockDim.x) {
        int b = idx / T_LEN, t = idx % T_LEN;
        int i = t >> 5, j = t & 31;
        float c = 0.0f;
        #pragma unroll
        for (int o = 0; o < NOBJ; o++) {
            const int* r = sreg[b * NOBJ + o];
            if (i >= r[0] && i < r[1] && j >= r[2] && j < r[3]) c += 1.0f;
        }
        g_cnt[idx] = c;
    }
}

__global__ __launch_bounds__(256)
void zero_afg_kernel() {
    int i = blockIdx.x * 256 + threadIdx.x;          // float4 index
    float4* p = (float4*)g_afg;
    if (i < (HH_TOT * T_LEN * CH) / 4) p[i] = make_float4(0.f, 0.f, 0.f, 0.f);
}

// ---------------- combine: qkv split + prompt projection GEMM ----------------
__global__ __launch_bounds__(256)
void combine_kernel(const float* __restrict__ qkv, const float* __restrict__ nemb,
                    const float* __restrict__ pemb, const float* __restrict__ W) {
    __shared__ float Ws[64 * 65];
    __shared__ __align__(16) float Es[64 * 68];
    const int g   = blockIdx.x;            // 0..23
    const int t0  = blockIdx.y * 64;
    const int zv  = blockIdx.z;
    const int b   = zv >> 1, var = zv & 1;
    const int head = g / 3, part = g % 3;
    const int cg0  = g * 64;
    const float* emb = (var ? pemb : nemb) + b * 64 * 1024;
    const int tid = threadIdx.x;

    for (int i = tid; i < 4096; i += 256) {
        int c = i >> 6, e = i & 63;
        Ws[c * 65 + e] = W[(cg0 + c) * 64 + e];
    }
    for (int i = tid; i < 4096; i += 256) {
        int e = i >> 6, t = i & 63;
        Es[e * 68 + t] = emb[e * 1024 + t0 + t];
    }
    __syncthreads();

    const int c = tid & 63, tg = tid >> 6;
    float acc[16];
    #pragma unroll
    for (int i = 0; i < 16; i++) acc[i] = 0.0f;

    #pragma unroll 4
    for (int e = 0; e < 64; e++) {
        float w = Ws[c * 65 + e];
        const float4* row = (const float4*)(Es + e * 68 + tg * 16);
        float4 a0 = row[0], a1 = row[1], a2 = row[2], a3 = row[3];
        acc[0]  += w * a0.x; acc[1]  += w * a0.y; acc[2]  += w * a0.z; acc[3]  += w * a0.w;
        acc[4]  += w * a1.x; acc[5]  += w * a1.y; acc[6]  += w * a1.z; acc[7]  += w * a1.w;
        acc[8]  += w * a2.x; acc[9]  += w * a2.y; acc[10] += w * a2.z; acc[11] += w * a2.w;
        acc[12] += w * a3.x; acc[13] += w * a3.y; acc[14] += w * a3.z; acc[15] += w * a3.w;
    }
    __syncthreads();
    const float* qk = qkv + (size_t)b * 1536 * 1024 + (size_t)cg0 * 1024 + t0;
    for (int i = tid; i < 4096; i += 256) {
        int cc = i >> 6, t = i & 63;
        Es[cc * 68 + t] = qk[cc * 1024 + t];
    }
    __syncthreads();

    float* dst;
    if (var == 0) dst = (part == 0 ? g_Qn : (part == 1 ? g_Kn : g_Vn));
    else          dst = (part == 0 ? g_Qf : (part == 1 ? g_Kf : g_Vf));
    dst += (b * NHEAD + head) * T_LEN * CH;
    const float sc = (part == 0) ? 0.125f : 1.0f;   // scale^2 folded into Q
    #pragma unroll
    for (int i = 0; i < 16; i++) {
        int t = tg * 16 + i;
        dst[(t0 + t) * CH + c] = (acc[i] + Es[c * 68 + t]) * sc;
    }
}

// ---------------- flash v2 core pieces ----------------
// thread grid: rowg = tid>>4 (8 groups of 8 q-rows), colg = tid&15 (16 groups of 8 k-cols)
// S held as 8 rows x 4 f32x2 col-pairs; O as 8 rows x 2 f32x2 ch-pairs (4 ch/thread).

__device__ __forceinline__ void fl_load_q_null(float* sm, const float* Qp, int q0, int tid) {
    const float4* Qg = (const float4*)(Qp + (size_t)q0 * CH);
    for (int idx = tid; idx < QT * 16; idx += 128) {
        int r = idx >> 4, c4 = idx & 15;
        float4 v = Qg[r * 16 + c4];
        float* d = sm + QS_OFF + r * 65 + c4 * 4;
        d[0] = v.x; d[1] = v.y; d[2] = v.z; d[3] = v.w;
    }
}

__device__ __forceinline__ void fl_load_kv_null(float* sm, const float* Kp, const float* Vp,
                                                int kt, int tid) {
    const float4* Kg = (const float4*)(Kp + (size_t)kt * KT * CH);
    const float4* Vg = (const float4*)(Vp + (size_t)kt * KT * CH);
    for (int idx = tid; idx < KT * 16; idx += 128) {
        int s = idx >> 4, c4 = idx & 15;
        int ps = s ^ (((s >> 5) & 3) << 1);
        float4 k = Kg[s * 16 + c4];
        float* kd = sm + KT_OFF + c4 * 4 * 130 + ps;
        kd[0] = k.x; kd[130] = k.y; kd[260] = k.z; kd[390] = k.w;
        float4 v = Vg[s * 16 + c4];
        float4 w = (c4 >= 8) ? make_float4(v.z, v.w, v.x, v.y) : v;
        *(float4*)(sm + V_OFF + s * 64 + c4 * 4) = w;
    }
}

// ---------------- flash_null (v2) ----------------
__global__ __launch_bounds__(128)
void flash_null_kernel() {
    extern __shared__ float sm[];
    const int bh = blockIdx.y;
    const int q0 = blockIdx.x * QT;
    const float* Qp = g_Qn + (size_t)bh * T_LEN * CH;
    const float* Kp = g_Kn + (size_t)bh * T_LEN * CH;
    const float* Vp = g_Vn + (size_t)bh * T_LEN * CH;
    const int tid = threadIdx.x;
    const int rowg = tid >> 4, colg = tid & 15;
    const int r0 = rowg * 8;

    int pcol[4], vcol[2];
    #pragma unroll
    for (int j = 0; j < 4; j++) {
        int s = colg * 8 + 2 * j;
        pcol[j] = s ^ (((s >> 5) & 3) << 1);
    }
    #pragma unroll
    for (int j = 0; j < 2; j++) {
        int cc = colg * 4 + 2 * j;
        vcol[j] = cc ^ (((cc >> 5) & 1) << 1);
    }

    fl_load_q_null(sm, Qp, q0, tid);

    ull O2[8][2];
    float m[8], l[8];
    #pragma unroll
    for (int i = 0; i < 8; i++) {
        m[i] = -1e30f; l[i] = 0.0f;
        O2[i][0] = 0ULL; O2[i][1] = 0ULL;
    }

    for (int kt = 0; kt < T_LEN / KT; kt++) {
        __syncthreads();
        fl_load_kv_null(sm, Kp, Vp, kt, tid);
        __syncthreads();

        // ---- S = Q K^T (f32x2 over col pairs) ----
        ull S2[8][4];
        #pragma unroll
        for (int i = 0; i < 8; i++)
            #pragma unroll
            for (int j = 0; j < 4; j++) S2[i][j] = 0ULL;

        const float* qb = sm + QS_OFF + r0 * 65;
        #pragma unroll 2
        for (int c = 0; c < CH; c += 2) {
            const float* kc0 = sm + KT_OFF + c * 130;
            const float* kc1 = kc0 + 130;
            ull ka[4], kb[4];
            #pragma unroll
            for (int j = 0; j < 4; j++) {
                ka[j] = *(const ull*)(kc0 + pcol[j]);
                kb[j] = *(const ull*)(kc1 + pcol[j]);
            }
            #pragma unroll
            for (int i = 0; i < 8; i++) {
                float qa = qb[i * 65 + c], qbv = qb[i * 65 + c + 1];
                ull qa2 = pk2(qa, qa), qb2 = pk2(qbv, qbv);
                #pragma unroll
                for (int j = 0; j < 4; j++) {
                    S2[i][j] = fma2(qa2, ka[j], S2[i][j]);
                    S2[i][j] = fma2(qb2, kb[j], S2[i][j]);
                }
            }
        }

        // ---- online softmax ----
        float sr[8][8];
        #pragma unroll
        for (int i = 0; i < 8; i++)
            #pragma unroll
            for (int j = 0; j < 4; j++) upk2(S2[i][j], sr[i][2 * j], sr[i][2 * j + 1]);

        #pragma unroll
        for (int i = 0; i < 8; i++) {
            float mx = sr[i][0];
            #pragma unroll
            for (int j = 1; j < 8; j++) mx = fmaxf(mx, sr[i][j]);
            #pragma unroll
            for (int off = 1; off < 16; off <<= 1) mx = fmaxf(mx, __shfl_xor_sync(0xffffffffu, mx, off));
            float mn = fmaxf(m[i], mx);
            float co = __expf(m[i] - mn);
            m[i] = mn;
            float rs = 0.0f;
            #pragma unroll
            for (int j = 0; j < 8; j++) { sr[i][j] = __expf(sr[i][j] - mn); rs += sr[i][j]; }
            #pragma unroll
            for (int off = 1; off < 16; off <<= 1) rs += __shfl_xor_sync(0xffffffffu, rs, off);
            l[i] = l[i] * co + rs;
            ull co2 = pk2(co, co);
            O2[i][0] = mul2(O2[i][0], co2);
            O2[i][1] = mul2(O2[i][1], co2);
        }

        __syncthreads();   // QK reads of KT_s done
        #pragma unroll
        for (int i = 0; i < 8; i++)
            #pragma unroll
            for (int j = 0; j < 4; j++)
                *(ull*)(sm + KT_OFF + (r0 + i) * 130 + pcol[j]) = pk2(sr[i][2 * j], sr[i][2 * j + 1]);
        __syncthreads();

        // ---- O += P V (f32x2 over ch pairs) ----
        #pragma unroll 2
        for (int s = 0; s < KT; s += 2) {
            int ps = s ^ (((s >> 5) & 3) << 1);
            const float* vr0 = sm + V_OFF + s * 64;
            const float* vr1 = vr0 + 64;
            ull v0a = *(const ull*)(vr0 + vcol[0]);
            ull v0b = *(const ull*)(vr0 + vcol[1]);
            ull v1a = *(const ull*)(vr1 + vcol[0]);
            ull v1b = *(const ull*)(vr1 + vcol[1]);
            #pragma unroll
            for (int i = 0; i < 8; i++) {
                ull p2 = *(const ull*)(sm + KT_OFF + (r0 + i) * 130 + ps);
                float pl, ph; upk2(p2, pl, ph);
                ull pl2 = pk2(pl, pl), ph2 = pk2(ph, ph);
                O2[i][0] = fma2(pl2, v0a, O2[i][0]);
                O2[i][1] = fma2(pl2, v0b, O2[i][1]);
                O2[i][0] = fma2(ph2, v1a, O2[i][0]);
                O2[i][1] = fma2(ph2, v1b, O2[i][1]);
            }
        }
    }

    float* Op = g_anull + (size_t)bh * T_LEN * CH;
    #pragma unroll
    for (int i = 0; i < 8; i++) {
        float inv = 1.0f / l[i];
        float o0, o1, o2, o3;
        upk2(O2[i][0], o0, o1);
        upk2(O2[i][1], o2, o3);
        *(float4*)(Op + (size_t)(q0 + r0 + i) * CH + colg * 4) =
            make_float4(o0 * inv, o1 * inv, o2 * inv, o3 * inv);
    }
}

// ---------------- flash_fg (v2 core + region gather + masking + atomic accum) ----------------
__global__ __launch_bounds__(128)
void flash_fg_kernel() {
    extern __shared__ float sm[];
    const int bh = blockIdx.z;
    const int o  = blockIdx.y;
    const int b  = bh >> 3;
    const int* box = g_regbox + (b * NOBJ + o) * 4;
    const int i0 = box[0], i1 = box[1], j0 = box[2], j1 = box[3];
    const int rw = j1 - j0;
    const int nR = (i1 - i0) * rw;
    const int qbase = blockIdx.x * QT;
    if (qbase >= nR) return;

    const float* Qp = g_Qf + (size_t)bh * T_LEN * CH;
    const float* Kp = g_Kf + (size_t)bh * T_LEN * CH;
    const float* Vp = g_Vf + (size_t)bh * T_LEN * CH;
    const int tid = threadIdx.x;
    const int rowg = tid >> 4, colg = tid & 15;
    const int r0 = rowg * 8;

    int pcol[4], vcol[2];
    #pragma unroll
    for (int j = 0; j < 4; j++) {
        int s = colg * 8 + 2 * j;
        pcol[j] = s ^ (((s >> 5) & 3) << 1);
    }
    #pragma unroll
    for (int j = 0; j < 2; j++) {
        int cc = colg * 4 + 2 * j;
        vcol[j] = cc ^ (((cc >> 5) & 1) << 1);
    }

    // gather Q region tokens
    for (int idx = tid; idx < QT * 16; idx += 128) {
        int r = idx >> 4, c4 = idx & 15;
        int u = qbase + r;
        float4 v = make_float4(0.f, 0.f, 0.f, 0.f);
        if (u < nR) {
            int t = (i0 + u / rw) * 32 + j0 + u % rw;
            v = ((const float4*)(Qp + (size_t)t * CH))[c4];
        }
        float* d = sm + QS_OFF + r * 65 + c4 * 4;
        d[0] = v.x; d[1] = v.y; d[2] = v.z; d[3] = v.w;
    }

    ull O2[8][2];
    float m[8], l[8];
    #pragma unroll
    for (int i = 0; i < 8; i++) {
        m[i] = -1e30f; l[i] = 0.0f;
        O2[i][0] = 0ULL; O2[i][1] = 0ULL;
    }

    const int nkt = (nR + KT - 1) / KT;
    for (int kt = 0; kt < nkt; kt++) {
        __syncthreads();
        for (int idx = tid; idx < KT * 16; idx += 128) {
            int s = idx >> 4, c4 = idx & 15;
            int sg = kt * KT + s;
            float4 k = make_float4(0.f, 0.f, 0.f, 0.f);
            float4 v = k;
            if (sg < nR) {
                int t = (i0 + sg / rw) * 32 + j0 + sg % rw;
                k = ((const float4*)(Kp + (size_t)t * CH))[c4];
                v = ((const float4*)(Vp + (size_t)t * CH))[c4];
            }
            int ps = s ^ (((s >> 5) & 3) << 1);
            float* kd = sm + KT_OFF + c4 * 4 * 130 + ps;
            kd[0] = k.x; kd[130] = k.y; kd[260] = k.z; kd[390] = k.w;
            float4 w = (c4 >= 8) ? make_float4(v.z, v.w, v.x, v.y) : v;
            *(float4*)(sm + V_OFF + s * 64 + c4 * 4) = w;
        }
        __syncthreads();

        ull S2[8][4];
        #pragma unroll
        for (int i = 0; i < 8; i++)
            #pragma unroll
            for (int j = 0; j < 4; j++) S2[i][j] = 0ULL;

        const float* qb = sm + QS_OFF + r0 * 65;
        #pragma unroll 2
        for (int c = 0; c < CH; c += 2) {
            const float* kc0 = sm + KT_OFF + c * 130;
            const float* kc1 = kc0 + 130;
            ull ka[4], kb[4];
            #pragma unroll
            for (int j = 0; j < 4; j++) {
                ka[j] = *(const ull*)(kc0 + pcol[j]);
                kb[j] = *(const ull*)(kc1 + pcol[j]);
            }
            #pragma unroll
            for (int i = 0; i < 8; i++) {
                float qa = qb[i * 65 + c], qbv = qb[i * 65 + c + 1];
                ull qa2 = pk2(qa, qa), qb2 = pk2(qbv, qbv);
                #pragma unroll
                for (int j = 0; j < 4; j++) {
                    S2[i][j] = fma2(qa2, ka[j], S2[i][j]);
                    S2[i][j] = fma2(qb2, kb[j], S2[i][j]);
                }
            }
        }

        float sr[8][8];
        #pragma unroll
        for (int i = 0; i < 8; i++)
            #pragma unroll
            for (int j = 0; j < 4; j++) upk2(S2[i][j], sr[i][2 * j], sr[i][2 * j + 1]);

        // mask columns beyond region
        #pragma unroll
        for (int j = 0; j < 8; j++) {
            if (kt * KT + colg * 8 + j >= nR) {
                #pragma unroll
                for (int i = 0; i < 8; i++) sr[i][j] = -1e30f;
            }
        }

        #pragma unroll
        for (int i = 0; i < 8; i++) {
            float mx = sr[i][0];
            #pragma unroll
            for (int j = 1; j < 8; j++) mx = fmaxf(mx, sr[i][j]);
            #pragma unroll
            for (int off = 1; off < 16; off <<= 1) mx = fmaxf(mx, __shfl_xor_sync(0xffffffffu, mx, off));
            float mn = fmaxf(m[i], mx);
            float co = __expf(m[i] - mn);
            m[i] = mn;
            float rs = 0.0f;
            #pragma unroll
            for (int j = 0; j < 8; j++) { sr[i][j] = __expf(sr[i][j] - mn); rs += sr[i][j]; }
            #pragma unroll
            for (int off = 1; off < 16; off <<= 1) rs += __shfl_xor_sync(0xffffffffu, rs, off);
            l[i] = l[i] * co + rs;
            ull co2 = pk2(co, co);
            O2[i][0] = mul2(O2[i][0], co2);
            O2[i][1] = mul2(O2[i][1], co2);
        }

        __syncthreads();
        #pragma unroll
        for (int i = 0; i < 8; i++)
            #pragma unroll
            for (int j = 0; j < 4; j++)
                *(ull*)(sm + KT_OFF + (r0 + i) * 130 + pcol[j]) = pk2(sr[i][2 * j], sr[i][2 * j + 1]);
        __syncthreads();

        #pragma unroll 2
        for (int s = 0; s < KT; s += 2) {
            int ps = s ^ (((s >> 5) & 3) << 1);
            const float* vr0 = sm + V_OFF + s * 64;
            const float* vr1 = vr0 + 64;
            ull v0a = *(const ull*)(vr0 + vcol[0]);
            ull v0b = *(const ull*)(vr0 + vcol[1]);
            ull v1a = *(const ull*)(vr1 + vcol[0]);
            ull v1b = *(const ull*)(vr1 + vcol[1]);
            #pragma unroll
            for (int i = 0; i < 8; i++) {
                ull p2 = *(const ull*)(sm + KT_OFF + (r0 + i) * 130 + ps);
                float pl, ph; upk2(p2, pl, ph);
                ull pl2 = pk2(pl, pl), ph2 = pk2(ph, ph);
                O2[i][0] = fma2(pl2, v0a, O2[i][0]);
                O2[i][1] = fma2(pl2, v0b, O2[i][1]);
                O2[i][0] = fma2(ph2, v1a, O2[i][0]);
                O2[i][1] = fma2(ph2, v1b, O2[i][1]);
            }
        }
    }

    float* Ap = g_afg + (size_t)bh * T_LEN * CH;
    #pragma unroll
    for (int i = 0; i < 8; i++) {
        int u = qbase + r0 + i;
        if (u < nR) {
            int t = (i0 + u / rw) * 32 + j0 + u % rw;
            float inv = 1.0f / l[i];
            float o0, o1, o2, o3;
            upk2(O2[i][0], o0, o1);
            upk2(O2[i][1], o2, o3);
            float* dp = Ap + (size_t)t * CH + colg * 4;
            atomicAdd(dp + 0, o0 * inv);
            atomicAdd(dp + 1, o1 * inv);
            atomicAdd(dp + 2, o2 * inv);
            atomicAdd(dp + 3, o3 * inv);
        }
    }
}

// ---------------- finalize: select + divide + transpose to (bs, 512, T) ----------------
__global__ __launch_bounds__(256)
void finalize_kernel(float* __restrict__ out) {
    __shared__ float smf[64 * 65];
    const int bh = blockIdx.y;
    const int t0 = blockIdx.x * 64;
    const int b = bh >> 3, h = bh & 7;
    const float* An = g_anull + (size_t)bh * T_LEN * CH;
    const float* Af = g_afg   + (size_t)bh * T_LEN * CH;
    const float* Cn = g_cnt + b * T_LEN;
    const int tid = threadIdx.x;
    for (int i = tid; i < 4096; i += 256) {
        int tt = i >> 6, c = i & 63;
        int t = t0 + tt;
        float cnt = Cn[t];
        float v = (cnt > 0.5f) ? Af[(size_t)t * CH + c] / cnt : An[(size_t)t * CH + c];
        smf[tt * 65 + c] = v;
    }
    __syncthreads();
    float* op = out + (size_t)b * 512 * 1024 + (size_t)h * 64 * 1024 + t0;
    for (int i = tid; i < 4096; i += 256) {
        int c = i >> 6, tt = i & 63;
        op[(size_t)c * 1024 + tt] = smf[tt * 65 + c];
    }
}

// ---------------- launch ----------------
extern "C" void kernel_launch(void* const* d_in, const int* in_sizes, int n_in,
                              void* d_out, int out_size) {
    const float* qkv  = (const float*)d_in[0];
    const float* bb   = (const float*)d_in[1];
    const float* nemb = (const float*)d_in[2];
    const float* pemb = (const float*)d_in[3];
    const float* W    = (const float*)d_in[4];
    float* out = (float*)d_out;

    cudaFuncSetAttribute(flash_null_kernel, cudaFuncAttributeMaxDynamicSharedMemorySize, SMEM_BYTES);
    cudaFuncSetAttribute(flash_fg_kernel,   cudaFuncAttributeMaxDynamicSharedMemorySize, SMEM_BYTES);

    prep_kernel<<<1, 256>>>(bb);
    zero_afg_kernel<<<(HH_TOT * T_LEN * CH / 4 + 255) / 256, 256>>>();
    combine_kernel<<<dim3(24, 16, 8), 256>>>(qkv, nemb, pemb, W);
    flash_null_kernel<<<dim3(T_LEN / QT, HH_TOT), 128, SMEM_BYTES>>>();
    flash_fg_kernel<<<dim3(T_LEN / QT, NOBJ, HH_TOT), 128, SMEM_BYTES>>>();
    finalize_kernel<<<dim3(T_LEN / 64, HH_TOT), 256>>>(out);
}